// round 1
// baseline (speedup 1.0000x reference)
#include <cuda_runtime.h>
#include <cuda_bf16.h>
#include <cstdint>

#define BB 2
#define NQ 300
#define NT 300
#define QP 320          // padded Q/T for GEMM tiles
#define IH 256
#define IW 256
#define HW 65536
#define NP 12544
#define SPLITK 8
#define KSPLIT (NP/SPLITK)   // 1568
#define PCHUNK 128
#define NCHUNKS (NP/PCHUNK)  // 98

// ---------------- scratch (static device arrays; no allocation) ----------------
__device__ __nv_bfloat16 g_predT[(size_t)BB*HW*QP];   // (b, y, x, q) bf16
__device__ __nv_bfloat16 g_tgtT [(size_t)BB*HW*QP];
__device__ __nv_bfloat16 g_om[(size_t)BB*NP*QP];      // sampled om, K-major [p][q]
__device__ __nv_bfloat16 g_s [(size_t)BB*NP*QP];      // sigmoid(om)
__device__ __nv_bfloat16 g_tm[(size_t)BB*NP*QP];      // sampled tm
__device__ float g_negP[BB*NCHUNKS*NQ];               // per-chunk partial softplus sums
__device__ float g_sP  [BB*NCHUNKS*NQ];
__device__ float g_tmP [BB*NCHUNKS*NT];
__device__ float g_negsum[BB*NQ];
__device__ float g_ssum  [BB*NQ];
__device__ float g_tmsum [BB*NT];
__device__ float g_C1p[(size_t)SPLITK*BB*NQ*NT];      // split-K partials
__device__ float g_C2p[(size_t)SPLITK*BB*NQ*NT];

static __device__ __forceinline__ uint32_t smem_u32(const void* p) {
    return (uint32_t)__cvta_generic_to_shared(p);
}

// ---------------- K1: transpose masks (b,q,y,x) f32 -> (b, y*x, qpad) bf16 ----
__global__ void k_transpose(const float* __restrict__ pred, const float* __restrict__ tgt) {
    __shared__ float tile[32][33];
    int bz = blockIdx.z;            // b*2 + isTgt
    int b = bz >> 1, isT = bz & 1;
    const float* src = isT ? tgt : pred;
    __nv_bfloat16* dst = isT ? g_tgtT : g_predT;
    int hw0 = blockIdx.x * 32;
    int q0 = blockIdx.y * 32;
    int tx = threadIdx.x, ty = threadIdx.y;
    #pragma unroll
    for (int i = 0; i < 4; i++) {
        int q = q0 + ty + i*8;
        float v = 0.0f;
        if (q < NQ) v = src[((size_t)(b*NQ + q))*HW + hw0 + tx];
        tile[ty + i*8][tx] = v;
    }
    __syncthreads();
    #pragma unroll
    for (int i = 0; i < 4; i++) {
        int hw = hw0 + ty + i*8;
        dst[((size_t)b*HW + hw)*QP + q0 + tx] = __float2bfloat16(tile[tx][ty + i*8]);
    }
}

// ---------------- K2: bilinear point sampling + fused row-sum partials -------
// block: 256 thr (8 warps), warp handles 16 points, lanes cover 320 q in 10 iters.
__global__ void k_sample(const float* __restrict__ pts) {
    __shared__ float red[8][QP];
    int bz = blockIdx.y;            // b*2 + isTgt
    int b = bz >> 1, isT = bz & 1;
    const __nv_bfloat16* src = (isT ? g_tgtT : g_predT) + (size_t)b*HW*QP;
    int chunk = blockIdx.x;
    int warp = threadIdx.x >> 5, lane = threadIdx.x & 31;

    float acc0[10], acc1[10];
    #pragma unroll
    for (int i = 0; i < 10; i++) { acc0[i] = 0.f; acc1[i] = 0.f; }

    for (int i = 0; i < 16; i++) {
        int p = chunk*PCHUNK + warp*16 + i;
        float2 pc = ((const float2*)pts)[(size_t)b*NP + p];
        float x = pc.x * IW - 0.5f, y = pc.y * IH - 0.5f;
        float x0f = floorf(x), y0f = floorf(y);
        float wx = x - x0f, wy = y - y0f;
        int ix0 = (int)x0f, iy0 = (int)y0f;
        float vx0 = (ix0 >= 0) ? 1.f : 0.f;
        float vx1 = (ix0 + 1 <= IW - 1) ? 1.f : 0.f;
        float vy0 = (iy0 >= 0) ? 1.f : 0.f;
        float vy1 = (iy0 + 1 <= IH - 1) ? 1.f : 0.f;
        int xc0 = max(ix0, 0), xc1 = min(ix0 + 1, IW - 1);
        int yc0 = max(iy0, 0), yc1 = min(iy0 + 1, IH - 1);
        float w00 = (1.f-wy)*(1.f-wx)*vy0*vx0;
        float w01 = (1.f-wy)*wx*vy0*vx1;
        float w10 = wy*(1.f-wx)*vy1*vx0;
        float w11 = wy*wx*vy1*vx1;
        const __nv_bfloat16* r00 = src + (size_t)(yc0*IW + xc0)*QP;
        const __nv_bfloat16* r01 = src + (size_t)(yc0*IW + xc1)*QP;
        const __nv_bfloat16* r10 = src + (size_t)(yc1*IW + xc0)*QP;
        const __nv_bfloat16* r11 = src + (size_t)(yc1*IW + xc1)*QP;
        size_t obase = ((size_t)b*NP + p)*QP;
        #pragma unroll
        for (int it = 0; it < 10; it++) {
            int q = it*32 + lane;
            float v = w00*__bfloat162float(r00[q]) + w01*__bfloat162float(r01[q])
                    + w10*__bfloat162float(r10[q]) + w11*__bfloat162float(r11[q]);
            if (!isT) {
                float s = 1.f / (1.f + __expf(-v));
                float sp = fmaxf(v, 0.f) + log1pf(__expf(-fabsf(v)));
                acc0[it] += sp;
                acc1[it] += s;
                g_om[obase + q] = __float2bfloat16(v);
                g_s [obase + q] = __float2bfloat16(s);
            } else {
                acc0[it] += v;
                g_tm[obase + q] = __float2bfloat16(v);
            }
        }
    }

    // deterministic CTA reduction -> per-chunk partials
    #pragma unroll
    for (int it = 0; it < 10; it++) red[warp][it*32 + lane] = acc0[it];
    __syncthreads();
    {
        float* dst = isT ? g_tmP : g_negP;
        for (int q = threadIdx.x; q < NQ; q += 256) {
            float sum = 0.f;
            #pragma unroll
            for (int w2 = 0; w2 < 8; w2++) sum += red[w2][q];
            dst[(b*NCHUNKS + chunk)*NQ + q] = sum;
        }
    }
    if (!isT) {
        __syncthreads();
        #pragma unroll
        for (int it = 0; it < 10; it++) red[warp][it*32 + lane] = acc1[it];
        __syncthreads();
        for (int q = threadIdx.x; q < NQ; q += 256) {
            float sum = 0.f;
            #pragma unroll
            for (int w2 = 0; w2 < 8; w2++) sum += red[w2][q];
            g_sP[(b*NCHUNKS + chunk)*NQ + q] = sum;
        }
    }
}

// ---------------- K3: fold chunk partials -> row sums (deterministic) --------
__global__ void k_colsum() {
    int idx = blockIdx.x * blockDim.x + threadIdx.x;
    if (idx >= 3*BB*NQ) return;
    int which = idx / (BB*NQ);
    int r = idx % (BB*NQ);
    int b = r / NQ, q = r % NQ;
    const float* src = (which == 0) ? g_negP : (which == 1) ? g_sP : g_tmP;
    float s = 0.f;
    for (int c = 0; c < NCHUNKS; c++) s += src[(b*NCHUNKS + c)*NQ + q];
    float* dst = (which == 0) ? g_negsum : (which == 1) ? g_ssum : g_tmsum;
    dst[b*NQ + q] = s;
}

// ---------------- K4: dual bf16 GEMM (C1 = om.tm^T, C2 = s.tm^T), split-K ----
__device__ __forceinline__ void ldsm4t(uint32_t* r, uint32_t addr) {
    asm volatile("ldmatrix.sync.aligned.m8n8.x4.trans.shared.b16 {%0,%1,%2,%3}, [%4];"
        : "=r"(r[0]), "=r"(r[1]), "=r"(r[2]), "=r"(r[3]) : "r"(addr));
}
__device__ __forceinline__ void mma16816(float* d, const uint32_t* a, const uint32_t* b) {
    asm volatile("mma.sync.aligned.m16n8k16.row.col.f32.bf16.bf16.f32 "
        "{%0,%1,%2,%3}, {%4,%5,%6,%7}, {%8,%9}, {%0,%1,%2,%3};"
        : "+f"(d[0]), "+f"(d[1]), "+f"(d[2]), "+f"(d[3])
        : "r"(a[0]), "r"(a[1]), "r"(a[2]), "r"(a[3]), "r"(b[0]), "r"(b[1]));
}

__global__ __launch_bounds__(128) void k_gemm() {
    __shared__ __nv_bfloat16 sO[16][72], sS[16][72], sB[16][72];
    int m0 = blockIdx.x * 64, n0 = blockIdx.y * 64;
    int b = blockIdx.z >> 3, sk = blockIdx.z & 7;
    int kbeg = sk * KSPLIT, kend = kbeg + KSPLIT;
    int tid = threadIdx.x, warp = tid >> 5, lane = tid & 31;
    int wm = (warp & 1) * 32, wn = (warp >> 1) * 32;
    int lrow = tid >> 3, lcol8 = (tid & 7) * 8;

    const __nv_bfloat16* gO = g_om + (size_t)b*NP*QP;
    const __nv_bfloat16* gS = g_s  + (size_t)b*NP*QP;
    const __nv_bfloat16* gB = g_tm + (size_t)b*NP*QP;

    float d1[2][4][4], d2[2][4][4];
    #pragma unroll
    for (int mi = 0; mi < 2; mi++)
        #pragma unroll
        for (int nj = 0; nj < 4; nj++)
            #pragma unroll
            for (int e = 0; e < 4; e++) { d1[mi][nj][e] = 0.f; d2[mi][nj][e] = 0.f; }

    // ldmatrix lane address components
    int a_kr = (lane & 7) + ((lane & 16) ? 8 : 0);
    int a_mc = ((lane >> 3) & 1) * 8;
    int b_kr = (lane & 7) + ((lane & 8) ? 8 : 0);
    int b_nc = ((lane & 16) ? 8 : 0);
    uint32_t aoAddr[2], asAddr[2], bAddr[2];
    #pragma unroll
    for (int mi = 0; mi < 2; mi++) {
        aoAddr[mi] = smem_u32(&sO[0][0]) + (uint32_t)(a_kr*72 + wm + mi*16 + a_mc)*2;
        asAddr[mi] = smem_u32(&sS[0][0]) + (uint32_t)(a_kr*72 + wm + mi*16 + a_mc)*2;
    }
    #pragma unroll
    for (int pr = 0; pr < 2; pr++)
        bAddr[pr] = smem_u32(&sB[0][0]) + (uint32_t)(b_kr*72 + wn + pr*16 + b_nc)*2;

    for (int k0 = kbeg; k0 < kend; k0 += 16) {
        __syncthreads();
        size_t ga = (size_t)(k0 + lrow)*QP;
        *(uint4*)&sO[lrow][lcol8] = *(const uint4*)&gO[ga + m0 + lcol8];
        *(uint4*)&sS[lrow][lcol8] = *(const uint4*)&gS[ga + m0 + lcol8];
        *(uint4*)&sB[lrow][lcol8] = *(const uint4*)&gB[ga + n0 + lcol8];
        __syncthreads();

        uint32_t bf[2][4], ao[2][4], as_[2][4];
        #pragma unroll
        for (int pr = 0; pr < 2; pr++) ldsm4t(bf[pr], bAddr[pr]);
        #pragma unroll
        for (int mi = 0; mi < 2; mi++) { ldsm4t(ao[mi], aoAddr[mi]); ldsm4t(as_[mi], asAddr[mi]); }

        #pragma unroll
        for (int mi = 0; mi < 2; mi++)
            #pragma unroll
            for (int nj = 0; nj < 4; nj++) {
                uint32_t bb_[2] = { bf[nj >> 1][(nj & 1)*2], bf[nj >> 1][(nj & 1)*2 + 1] };
                mma16816(d1[mi][nj], ao[mi], bb_);
                mma16816(d2[mi][nj], as_[mi], bb_);
            }
    }

    float* C1 = g_C1p + (size_t)(sk*BB + b)*NQ*NT;
    float* C2 = g_C2p + (size_t)(sk*BB + b)*NQ*NT;
    int r = lane >> 2, c2 = (lane & 3)*2;
    #pragma unroll
    for (int mi = 0; mi < 2; mi++)
        #pragma unroll
        for (int nj = 0; nj < 4; nj++) {
            int m = m0 + wm + mi*16 + r;
            int n = n0 + wn + nj*8 + c2;
            if (m < NQ) {
                if (n     < NT) { C1[(size_t)m*NT + n]     = d1[mi][nj][0]; C2[(size_t)m*NT + n]     = d2[mi][nj][0]; }
                if (n + 1 < NT) { C1[(size_t)m*NT + n + 1] = d1[mi][nj][1]; C2[(size_t)m*NT + n + 1] = d2[mi][nj][1]; }
            }
            if (m + 8 < NQ) {
                if (n     < NT) { C1[(size_t)(m+8)*NT + n]     = d1[mi][nj][2]; C2[(size_t)(m+8)*NT + n]     = d2[mi][nj][2]; }
                if (n + 1 < NT) { C1[(size_t)(m+8)*NT + n + 1] = d1[mi][nj][3]; C2[(size_t)(m+8)*NT + n + 1] = d2[mi][nj][3]; }
            }
        }
}

// ---------------- K5: final cost (mask + dice + bbox L1 + giou) --------------
__global__ void k_final(const float* __restrict__ pb, const float* __restrict__ tb,
                        float* __restrict__ out) {
    int idx = blockIdx.x * 256 + threadIdx.x;
    if (idx >= BB*NQ*NT) return;
    int t = idx % NT; int r = idx / NT; int q = r % NQ; int b = r / NQ;

    float c1 = 0.f, c2 = 0.f;
    #pragma unroll
    for (int sk = 0; sk < SPLITK; sk++) {
        size_t off = ((size_t)(sk*BB + b)*NQ + q)*NT + t;
        c1 += g_C1p[off]; c2 += g_C2p[off];
    }
    float neg = g_negsum[b*NQ + q], ss = g_ssum[b*NQ + q], ts = g_tmsum[b*NT + t];
    float cost_mask = (neg - c1) * (1.0f/(float)NP);
    float cost_dice = 1.f - (2.f*c2 + 1.f) / (ss + ts + 1.f);

    float4 pbox = ((const float4*)pb)[(size_t)b*NQ + q];
    float4 tbox = ((const float4*)tb)[(size_t)b*NT + t];
    float l1 = fabsf(pbox.x - tbox.x) + fabsf(pbox.y - tbox.y)
             + fabsf(pbox.z - tbox.z) + fabsf(pbox.w - tbox.w);

    float ax0 = pbox.x - 0.5f*pbox.z, ay0 = pbox.y - 0.5f*pbox.w;
    float ax1 = pbox.x + 0.5f*pbox.z, ay1 = pbox.y + 0.5f*pbox.w;
    float bx0 = tbox.x - 0.5f*tbox.z, by0 = tbox.y - 0.5f*tbox.w;
    float bx1 = tbox.x + 0.5f*tbox.z, by1 = tbox.y + 0.5f*tbox.w;
    float areaA = (ax1 - ax0)*(ay1 - ay0);
    float areaB = (bx1 - bx0)*(by1 - by0);
    float iw = fmaxf(fminf(ax1, bx1) - fmaxf(ax0, bx0), 0.f);
    float ih = fmaxf(fminf(ay1, by1) - fmaxf(ay0, by0), 0.f);
    float inter = iw * ih;
    float uni = areaA + areaB - inter;
    float iou = inter / uni;
    float ew = fmaxf(fmaxf(ax1, bx1) - fminf(ax0, bx0), 0.f);
    float eh = fmaxf(fmaxf(ay1, by1) - fminf(ay0, by0), 0.f);
    float areaE = ew * eh;
    float giou = iou - (areaE - uni) / areaE;

    out[idx] = 5.f*cost_mask + 5.f*cost_dice + 5.f*l1 - 2.f*giou;
}

// ---------------- launch ------------------------------------------------------
extern "C" void kernel_launch(void* const* d_in, const int* in_sizes, int n_in,
                              void* d_out, int out_size) {
    const float* pred_masks = (const float*)d_in[0];
    const float* tgt_masks  = (const float*)d_in[1];
    const float* pred_boxes = (const float*)d_in[2];
    const float* tgt_boxes  = (const float*)d_in[3];
    const float* pts        = (const float*)d_in[4];
    float* out = (float*)d_out;

    k_transpose<<<dim3(HW/32, QP/32, 4), dim3(32, 8)>>>(pred_masks, tgt_masks);
    k_sample<<<dim3(NCHUNKS, 4), 256>>>(pts);
    k_colsum<<<8, 256>>>();
    k_gemm<<<dim3(5, 5, BB*SPLITK), 128>>>();
    k_final<<<(BB*NQ*NT + 255)/256, 256>>>(pred_boxes, tgt_boxes, out);
}

// round 2
// speedup vs baseline: 1.4187x; 1.4187x over previous
#include <cuda_runtime.h>
#include <cuda_bf16.h>
#include <cstdint>

#define BB 2
#define NQ 300
#define NT 300
#define QP 320
#define IH 256
#define IW 256
#define HW 65536
#define NP 12544
#define SPLITK 8
#define KSPLIT (NP/SPLITK)      // 1568
#define KSTAGE 32
#define NSTAGES (KSPLIT/KSTAGE) // 49

// ---------------- scratch ----------------
__device__ __nv_bfloat16 g_om[(size_t)BB*QP*NP];   // [b][q][p], p contiguous
__device__ __nv_bfloat16 g_s [(size_t)BB*QP*NP];
__device__ __nv_bfloat16 g_tm[(size_t)BB*QP*NP];
__device__ float g_negsum[BB*NQ];
__device__ float g_ssum  [BB*NQ];
__device__ float g_tmsum [BB*NT];
__device__ float g_C1p[(size_t)SPLITK*BB*NQ*NT];
__device__ float g_C2p[(size_t)SPLITK*BB*NQ*NT];

static __device__ __forceinline__ uint32_t smem_u32(const void* p) {
    return (uint32_t)__cvta_generic_to_shared(p);
}
static __device__ __forceinline__ void cpasync16(uint32_t dst, const void* src) {
    asm volatile("cp.async.cg.shared.global [%0], [%1], 16;\n" :: "r"(dst), "l"(src));
}
static __device__ __forceinline__ void cp_commit() { asm volatile("cp.async.commit_group;\n"); }
template<int N> static __device__ __forceinline__ void cp_wait() {
    asm volatile("cp.async.wait_group %0;\n" :: "n"(N));
}

// ---------- K1: per-mask smem-resident sampling + fused full row sums --------
// grid (NQ, BB, 2): one CTA per (q, b, isTgt). 512 threads.
__global__ void k_sample(const float* __restrict__ pred, const float* __restrict__ tgt,
                         const float* __restrict__ pts) {
    extern __shared__ char sraw[];
    __nv_bfloat16* smask = (__nv_bfloat16*)sraw;
    float* rbuf = (float*)(sraw + HW*2);
    int q = blockIdx.x, b = blockIdx.y, isT = blockIdx.z;
    int tid = threadIdx.x;

    const float* src = (isT ? tgt : pred) + ((size_t)(b*NQ + q))*HW;
    const float4* s4 = (const float4*)src;
    #pragma unroll 4
    for (int i = tid; i < HW/4; i += 512) {
        float4 v = s4[i];
        __nv_bfloat162 p0 = __floats2bfloat162_rn(v.x, v.y);
        __nv_bfloat162 p1 = __floats2bfloat162_rn(v.z, v.w);
        uint2 u;
        u.x = *(uint32_t*)&p0; u.y = *(uint32_t*)&p1;
        ((uint2*)smask)[i] = u;
    }
    __syncthreads();

    const float2* pp = ((const float2*)pts) + (size_t)b*NP;
    size_t obase = ((size_t)(b*QP + q))*NP;
    float accA = 0.f, accB = 0.f;

    for (int p = tid; p < NP; p += 512) {
        float2 pc = pp[p];
        float x = pc.x * IW - 0.5f, y = pc.y * IH - 0.5f;
        float x0f = floorf(x), y0f = floorf(y);
        float wx = x - x0f, wy = y - y0f;
        int ix0 = (int)x0f, iy0 = (int)y0f;
        float vx0 = (ix0 >= 0) ? 1.f : 0.f;
        float vx1 = (ix0 + 1 <= IW - 1) ? 1.f : 0.f;
        float vy0 = (iy0 >= 0) ? 1.f : 0.f;
        float vy1 = (iy0 + 1 <= IH - 1) ? 1.f : 0.f;
        int xc0 = max(ix0, 0), xc1 = min(ix0 + 1, IW - 1);
        int yc0 = max(iy0, 0), yc1 = min(iy0 + 1, IH - 1);
        float w00 = (1.f-wy)*(1.f-wx)*vy0*vx0;
        float w01 = (1.f-wy)*wx*vy0*vx1;
        float w10 = wy*(1.f-wx)*vy1*vx0;
        float w11 = wy*wx*vy1*vx1;
        float v = w00*__bfloat162float(smask[yc0*IW + xc0])
                + w01*__bfloat162float(smask[yc0*IW + xc1])
                + w10*__bfloat162float(smask[yc1*IW + xc0])
                + w11*__bfloat162float(smask[yc1*IW + xc1]);
        if (!isT) {
            float s = 1.f / (1.f + __expf(-v));
            float sp = fmaxf(v, 0.f) + log1pf(__expf(-fabsf(v)));
            accA += sp; accB += s;
            g_om[obase + p] = __float2bfloat16(v);
            g_s [obase + p] = __float2bfloat16(s);
        } else {
            accA += v;
            g_tm[obase + p] = __float2bfloat16(v);
        }
    }

    // deterministic tree reduction
    rbuf[tid] = accA; __syncthreads();
    #pragma unroll
    for (int o = 256; o > 0; o >>= 1) { if (tid < o) rbuf[tid] += rbuf[tid + o]; __syncthreads(); }
    float sumA = rbuf[0];
    __syncthreads();
    if (!isT) {
        rbuf[tid] = accB; __syncthreads();
        #pragma unroll
        for (int o = 256; o > 0; o >>= 1) { if (tid < o) rbuf[tid] += rbuf[tid + o]; __syncthreads(); }
        if (tid == 0) { g_negsum[b*NQ + q] = sumA; g_ssum[b*NQ + q] = rbuf[0]; }
    } else {
        if (tid == 0) g_tmsum[b*NT + q] = sumA;
    }
}

// ---------------- K2: dual bf16 GEMM, double-buffered cp.async ---------------
__device__ __forceinline__ void ldsm4(uint32_t* r, uint32_t addr) {
    asm volatile("ldmatrix.sync.aligned.m8n8.x4.shared.b16 {%0,%1,%2,%3}, [%4];"
        : "=r"(r[0]), "=r"(r[1]), "=r"(r[2]), "=r"(r[3]) : "r"(addr));
}
__device__ __forceinline__ void mma16816(float* d, const uint32_t* a, uint32_t b0, uint32_t b1) {
    asm volatile("mma.sync.aligned.m16n8k16.row.col.f32.bf16.bf16.f32 "
        "{%0,%1,%2,%3}, {%4,%5,%6,%7}, {%8,%9}, {%0,%1,%2,%3};"
        : "+f"(d[0]), "+f"(d[1]), "+f"(d[2]), "+f"(d[3])
        : "r"(a[0]), "r"(a[1]), "r"(a[2]), "r"(a[3]), "r"(b0), "r"(b1));
}

#define TPAD 40                      // smem row stride (elements) -> 80B, conflict-free
#define TILE (64*TPAD)

__global__ __launch_bounds__(128) void k_gemm() {
    __shared__ __nv_bfloat16 sbuf[2][3][TILE];   // [stage][om,s,tm][64 rows x 40]
    int m0 = blockIdx.x * 64, n0 = blockIdx.y * 64;
    int b = blockIdx.z >> 3, sk = blockIdx.z & 7;
    int kbeg = sk * KSPLIT;
    int tid = threadIdx.x, warp = tid >> 5, lane = tid & 31;
    int wm = (warp & 1) * 32, wn = (warp >> 1) * 32;

    const __nv_bfloat16* gA1 = g_om + (size_t)b*QP*NP;   // om rows [m][p]
    const __nv_bfloat16* gA2 = g_s  + (size_t)b*QP*NP;
    const __nv_bfloat16* gB  = g_tm + (size_t)b*QP*NP;

    // load mapping: 128 thr, 4 thr/row (16B chunks), 32 rows/iter, 2 iters/tile
    int lrow = tid >> 2, lcol = (tid & 3) * 8;

    auto load_stage = [&](int buf, int k0) {
        #pragma unroll
        for (int it = 0; it < 2; it++) {
            int row = lrow + it*32;
            uint32_t d1 = smem_u32(&sbuf[buf][0][row*TPAD + lcol]);
            uint32_t d2 = smem_u32(&sbuf[buf][1][row*TPAD + lcol]);
            uint32_t d3 = smem_u32(&sbuf[buf][2][row*TPAD + lcol]);
            cpasync16(d1, gA1 + (size_t)(m0 + row)*NP + k0 + lcol);
            cpasync16(d2, gA2 + (size_t)(m0 + row)*NP + k0 + lcol);
            cpasync16(d3, gB  + (size_t)(n0 + row)*NP + k0 + lcol);
        }
    };

    float d1[2][4][4], d2[2][4][4];
    #pragma unroll
    for (int mi = 0; mi < 2; mi++)
        #pragma unroll
        for (int nj = 0; nj < 4; nj++)
            #pragma unroll
            for (int e = 0; e < 4; e++) { d1[mi][nj][e] = 0.f; d2[mi][nj][e] = 0.f; }

    // ldmatrix lane offsets
    int a_r = lane & 15, a_c = ((lane >> 4) & 1) * 8;                 // A non-trans x4
    int b_r = (lane & 7) + (((lane & 16) ? 8 : 0)), b_c = ((lane & 8) ? 8 : 0);  // B x4

    load_stage(0, kbeg);
    cp_commit();

    for (int s = 0; s < NSTAGES; s++) {
        int cur = s & 1;
        if (s + 1 < NSTAGES) {
            load_stage(cur ^ 1, kbeg + (s + 1)*KSTAGE);
            cp_commit();
            cp_wait<1>();
        } else {
            cp_wait<0>();
        }
        __syncthreads();

        const __nv_bfloat16* t1 = sbuf[cur][0];
        const __nv_bfloat16* t2 = sbuf[cur][1];
        const __nv_bfloat16* tB = sbuf[cur][2];
        #pragma unroll
        for (int kk = 0; kk < 2; kk++) {
            uint32_t ao[2][4], as_[2][4], bf[2][4];
            #pragma unroll
            for (int mi = 0; mi < 2; mi++) {
                uint32_t off = (uint32_t)((wm + mi*16 + a_r)*TPAD + kk*16 + a_c)*2;
                ldsm4(ao[mi],  smem_u32(t1) + off);
                ldsm4(as_[mi], smem_u32(t2) + off);
            }
            #pragma unroll
            for (int nb = 0; nb < 2; nb++) {
                uint32_t off = (uint32_t)((wn + nb*16 + b_r)*TPAD + kk*16 + b_c)*2;
                ldsm4(bf[nb], smem_u32(tB) + off);
            }
            #pragma unroll
            for (int mi = 0; mi < 2; mi++)
                #pragma unroll
                for (int nj = 0; nj < 4; nj++) {
                    uint32_t b0 = bf[nj >> 1][(nj & 1)*2], b1 = bf[nj >> 1][(nj & 1)*2 + 1];
                    mma16816(d1[mi][nj], ao[mi],  b0, b1);
                    mma16816(d2[mi][nj], as_[mi], b0, b1);
                }
        }
        __syncthreads();
    }

    float* C1 = g_C1p + (size_t)(sk*BB + b)*NQ*NT;
    float* C2 = g_C2p + (size_t)(sk*BB + b)*NQ*NT;
    int r = lane >> 2, c2 = (lane & 3)*2;
    #pragma unroll
    for (int mi = 0; mi < 2; mi++)
        #pragma unroll
        for (int nj = 0; nj < 4; nj++) {
            int m = m0 + wm + mi*16 + r;
            int n = n0 + wn + nj*8 + c2;
            if (m < NQ) {
                if (n     < NT) { C1[(size_t)m*NT + n]     = d1[mi][nj][0]; C2[(size_t)m*NT + n]     = d2[mi][nj][0]; }
                if (n + 1 < NT) { C1[(size_t)m*NT + n + 1] = d1[mi][nj][1]; C2[(size_t)m*NT + n + 1] = d2[mi][nj][1]; }
            }
            if (m + 8 < NQ) {
                if (n     < NT) { C1[(size_t)(m+8)*NT + n]     = d1[mi][nj][2]; C2[(size_t)(m+8)*NT + n]     = d2[mi][nj][2]; }
                if (n + 1 < NT) { C1[(size_t)(m+8)*NT + n + 1] = d1[mi][nj][3]; C2[(size_t)(m+8)*NT + n + 1] = d2[mi][nj][3]; }
            }
        }
}

// ---------------- K3: final cost --------------------------------------------
__global__ void k_final(const float* __restrict__ pb, const float* __restrict__ tb,
                        float* __restrict__ out) {
    int idx = blockIdx.x * 256 + threadIdx.x;
    if (idx >= BB*NQ*NT) return;
    int t = idx % NT; int r = idx / NT; int q = r % NQ; int b = r / NQ;

    float c1 = 0.f, c2 = 0.f;
    #pragma unroll
    for (int sk = 0; sk < SPLITK; sk++) {
        size_t off = ((size_t)(sk*BB + b)*NQ + q)*NT + t;
        c1 += g_C1p[off]; c2 += g_C2p[off];
    }
    float neg = g_negsum[b*NQ + q], ss = g_ssum[b*NQ + q], ts = g_tmsum[b*NT + t];
    float cost_mask = (neg - c1) * (1.0f/(float)NP);
    float cost_dice = 1.f - (2.f*c2 + 1.f) / (ss + ts + 1.f);

    float4 pbox = ((const float4*)pb)[(size_t)b*NQ + q];
    float4 tbox = ((const float4*)tb)[(size_t)b*NT + t];
    float l1 = fabsf(pbox.x - tbox.x) + fabsf(pbox.y - tbox.y)
             + fabsf(pbox.z - tbox.z) + fabsf(pbox.w - tbox.w);

    float ax0 = pbox.x - 0.5f*pbox.z, ay0 = pbox.y - 0.5f*pbox.w;
    float ax1 = pbox.x + 0.5f*pbox.z, ay1 = pbox.y + 0.5f*pbox.w;
    float bx0 = tbox.x - 0.5f*tbox.z, by0 = tbox.y - 0.5f*tbox.w;
    float bx1 = tbox.x + 0.5f*tbox.z, by1 = tbox.y + 0.5f*tbox.w;
    float areaA = (ax1 - ax0)*(ay1 - ay0);
    float areaB = (bx1 - bx0)*(by1 - by0);
    float iw = fmaxf(fminf(ax1, bx1) - fmaxf(ax0, bx0), 0.f);
    float ih = fmaxf(fminf(ay1, by1) - fmaxf(ay0, by0), 0.f);
    float inter = iw * ih;
    float uni = areaA + areaB - inter;
    float iou = inter / uni;
    float ew = fmaxf(fmaxf(ax1, bx1) - fminf(ax0, bx0), 0.f);
    float eh = fmaxf(fmaxf(ay1, by1) - fminf(ay0, by0), 0.f);
    float areaE = ew * eh;
    float giou = iou - (areaE - uni) / areaE;

    out[idx] = 5.f*cost_mask + 5.f*cost_dice + 5.f*l1 - 2.f*giou;
}

// ---------------- launch ------------------------------------------------------
extern "C" void kernel_launch(void* const* d_in, const int* in_sizes, int n_in,
                              void* d_out, int out_size) {
    const float* pred_masks = (const float*)d_in[0];
    const float* tgt_masks  = (const float*)d_in[1];
    const float* pred_boxes = (const float*)d_in[2];
    const float* tgt_boxes  = (const float*)d_in[3];
    const float* pts        = (const float*)d_in[4];
    float* out = (float*)d_out;

    const int smem_sample = HW*2 + 512*4;
    cudaFuncSetAttribute(k_sample, cudaFuncAttributeMaxDynamicSharedMemorySize, smem_sample);

    k_sample<<<dim3(NQ, BB, 2), 512, smem_sample>>>(pred_masks, tgt_masks, pts);
    k_gemm<<<dim3(5, 5, BB*SPLITK), 128>>>();
    k_final<<<(BB*NQ*NT + 255)/256, 256>>>(pred_boxes, tgt_boxes, out);
}

// round 3
// speedup vs baseline: 1.4942x; 1.0532x over previous
#include <cuda_runtime.h>
#include <cuda_bf16.h>
#include <cstdint>

#define BB 2
#define NQ 300
#define NT 300
#define QP 320
#define IH 256
#define IW 256
#define HW 65536
#define NP 12544
#define SPLITK 8
#define KSPLIT (NP/SPLITK)      // 1568
#define KSTAGE 32
#define NSTAGES (KSPLIT/KSTAGE) // 49

// ---------------- scratch ----------------
__device__ __nv_bfloat16 g_om[(size_t)BB*QP*NP];   // [b][q][p]
__device__ __nv_bfloat16 g_s [(size_t)BB*QP*NP];
__device__ __nv_bfloat16 g_tm[(size_t)BB*QP*NP];
__device__ float g_negP[2*BB*NQ];                  // per-half partials
__device__ float g_sP  [2*BB*NQ];
__device__ float g_tmsum[BB*NT];
__device__ float g_C1p[(size_t)SPLITK*BB*NQ*NT];
__device__ float g_C2p[(size_t)SPLITK*BB*NQ*NT];

static __device__ __forceinline__ uint32_t smem_u32(const void* p) {
    return (uint32_t)__cvta_generic_to_shared(p);
}
static __device__ __forceinline__ void cpasync16(uint32_t dst, const void* src) {
    asm volatile("cp.async.cg.shared.global [%0], [%1], 16;\n" :: "r"(dst), "l"(src));
}
static __device__ __forceinline__ void cp_commit() { asm volatile("cp.async.commit_group;\n"); }
template<int N> static __device__ __forceinline__ void cp_wait() {
    asm volatile("cp.async.wait_group %0;\n" :: "n"(N));
}

// ---------- K1a: pred sampler, half-mask per CTA (129 rows, 66KB smem) -------
// grid (NQ, BB, 2 halves), 1024 threads, 2 CTAs/SM.
__global__ __launch_bounds__(1024, 2)
void k_sample_pred(const float* __restrict__ pred, const float* __restrict__ pts) {
    extern __shared__ char sraw[];
    __nv_bfloat16* smask = (__nv_bfloat16*)sraw;   // up to 129*256 bf16
    float* rbuf = (float*)(sraw + 129*IW*2);       // 1024 floats
    int q = blockIdx.x, b = blockIdx.y, h = blockIdx.z;
    int tid = threadIdx.x;

    int rows = h ? 128 : 129;                       // guard row only for half 0
    const float* src = pred + ((size_t)(b*NQ + q))*HW + (size_t)h*128*IW;
    const float4* s4 = (const float4*)src;
    int n4 = rows * IW / 4;
    #pragma unroll 4
    for (int i = tid; i < n4; i += 1024) {
        float4 v = s4[i];
        __nv_bfloat162 p0 = __floats2bfloat162_rn(v.x, v.y);
        __nv_bfloat162 p1 = __floats2bfloat162_rn(v.z, v.w);
        uint2 u; u.x = *(uint32_t*)&p0; u.y = *(uint32_t*)&p1;
        ((uint2*)smask)[i] = u;
    }
    __syncthreads();

    const float2* pp = ((const float2*)pts) + (size_t)b*NP;
    size_t obase = ((size_t)(b*QP + q))*NP;
    float accA = 0.f, accB = 0.f;

    for (int p = tid; p < NP; p += 1024) {
        float2 pc = pp[p];
        float y = pc.y * IH - 0.5f;
        float y0f = floorf(y);
        int iy0 = (int)y0f;
        bool own = h ? (iy0 >= 128) : (iy0 < 128);
        if (!own) continue;
        float x = pc.x * IW - 0.5f;
        float x0f = floorf(x);
        float wx = x - x0f, wy = y - y0f;
        int ix0 = (int)x0f;
        float vx0 = (ix0 >= 0) ? 1.f : 0.f;
        float vx1 = (ix0 + 1 <= IW - 1) ? 1.f : 0.f;
        float vy0 = (iy0 >= 0) ? 1.f : 0.f;
        float vy1 = (iy0 + 1 <= IH - 1) ? 1.f : 0.f;
        int xc0 = max(ix0, 0), xc1 = min(ix0 + 1, IW - 1);
        int yl0 = max(iy0, 0) - h*128;
        int yl1 = min(iy0 + 1, IH - 1) - h*128;
        float w00 = (1.f-wy)*(1.f-wx)*vy0*vx0;
        float w01 = (1.f-wy)*wx*vy0*vx1;
        float w10 = wy*(1.f-wx)*vy1*vx0;
        float w11 = wy*wx*vy1*vx1;
        float v = w00*__bfloat162float(smask[yl0*IW + xc0])
                + w01*__bfloat162float(smask[yl0*IW + xc1])
                + w10*__bfloat162float(smask[yl1*IW + xc0])
                + w11*__bfloat162float(smask[yl1*IW + xc1]);
        // fast softplus + sigmoid sharing one exp
        float e = __expf(-fabsf(v));
        float t = 1.f + e;
        float inv = __fdividef(1.f, t);
        float s = (v >= 0.f) ? inv : e * inv;
        float sp = fmaxf(v, 0.f) + __logf(t);
        accA += sp; accB += s;
        g_om[obase + p] = __float2bfloat16(v);
        g_s [obase + p] = __float2bfloat16(s);
    }

    rbuf[tid] = accA; __syncthreads();
    #pragma unroll
    for (int o = 512; o > 0; o >>= 1) { if (tid < o) rbuf[tid] += rbuf[tid + o]; __syncthreads(); }
    float sumA = rbuf[0];
    __syncthreads();
    rbuf[tid] = accB; __syncthreads();
    #pragma unroll
    for (int o = 512; o > 0; o >>= 1) { if (tid < o) rbuf[tid] += rbuf[tid + o]; __syncthreads(); }
    if (tid == 0) {
        g_negP[h*BB*NQ + b*NQ + q] = sumA;
        g_sP  [h*BB*NQ + b*NQ + q] = rbuf[0];
    }
}

// ---------- K1b: tgt sampler, bit-packed mask (8KB smem), 4 CTAs/SM ----------
__global__ __launch_bounds__(512, 4)
void k_sample_tgt(const float* __restrict__ tgt, const float* __restrict__ pts) {
    __shared__ uint32_t sbits[HW/32];   // 2048 words = 8KB
    __shared__ float rbuf[512];
    int q = blockIdx.x, b = blockIdx.y;
    int tid = threadIdx.x, warp = tid >> 5, lane = tid & 31;

    const float* src = tgt + ((size_t)(b*NT + q))*HW;
    #pragma unroll 4
    for (int w = warp; w < HW/32; w += 16) {
        float v = src[w*32 + lane];
        uint32_t m = __ballot_sync(0xffffffffu, v != 0.0f);
        if (lane == 0) sbits[w] = m;
    }
    __syncthreads();

    const float2* pp = ((const float2*)pts) + (size_t)b*NP;
    size_t obase = ((size_t)(b*QP + q))*NP;
    float acc = 0.f;

    for (int p = tid; p < NP; p += 512) {
        float2 pc = pp[p];
        float x = pc.x * IW - 0.5f, y = pc.y * IH - 0.5f;
        float x0f = floorf(x), y0f = floorf(y);
        float wx = x - x0f, wy = y - y0f;
        int ix0 = (int)x0f, iy0 = (int)y0f;
        float vx0 = (ix0 >= 0) ? 1.f : 0.f;
        float vx1 = (ix0 + 1 <= IW - 1) ? 1.f : 0.f;
        float vy0 = (iy0 >= 0) ? 1.f : 0.f;
        float vy1 = (iy0 + 1 <= IH - 1) ? 1.f : 0.f;
        int xc0 = max(ix0, 0), xc1 = min(ix0 + 1, IW - 1);
        int yc0 = max(iy0, 0), yc1 = min(iy0 + 1, IH - 1);
        int r0 = yc0 * IW, r1 = yc1 * IW;
        float b00 = (float)((sbits[(r0 + xc0) >> 5] >> (xc0 & 31)) & 1u);
        float b01 = (float)((sbits[(r0 + xc1) >> 5] >> (xc1 & 31)) & 1u);
        float b10 = (float)((sbits[(r1 + xc0) >> 5] >> (xc0 & 31)) & 1u);
        float b11 = (float)((sbits[(r1 + xc1) >> 5] >> (xc1 & 31)) & 1u);
        float w00 = (1.f-wy)*(1.f-wx)*vy0*vx0;
        float w01 = (1.f-wy)*wx*vy0*vx1;
        float w10 = wy*(1.f-wx)*vy1*vx0;
        float w11 = wy*wx*vy1*vx1;
        float v = w00*b00 + w01*b01 + w10*b10 + w11*b11;
        acc += v;
        g_tm[obase + p] = __float2bfloat16(v);
    }

    rbuf[tid] = acc; __syncthreads();
    #pragma unroll
    for (int o = 256; o > 0; o >>= 1) { if (tid < o) rbuf[tid] += rbuf[tid + o]; __syncthreads(); }
    if (tid == 0) g_tmsum[b*NT + q] = rbuf[0];
}

// ---------------- K2: dual bf16 GEMM, double-buffered cp.async ---------------
__device__ __forceinline__ void ldsm4(uint32_t* r, uint32_t addr) {
    asm volatile("ldmatrix.sync.aligned.m8n8.x4.shared.b16 {%0,%1,%2,%3}, [%4];"
        : "=r"(r[0]), "=r"(r[1]), "=r"(r[2]), "=r"(r[3]) : "r"(addr));
}
__device__ __forceinline__ void mma16816(float* d, const uint32_t* a, uint32_t b0, uint32_t b1) {
    asm volatile("mma.sync.aligned.m16n8k16.row.col.f32.bf16.bf16.f32 "
        "{%0,%1,%2,%3}, {%4,%5,%6,%7}, {%8,%9}, {%0,%1,%2,%3};"
        : "+f"(d[0]), "+f"(d[1]), "+f"(d[2]), "+f"(d[3])
        : "r"(a[0]), "r"(a[1]), "r"(a[2]), "r"(a[3]), "r"(b0), "r"(b1));
}

#define TPAD 40
#define TILE (64*TPAD)

__global__ __launch_bounds__(128) void k_gemm() {
    __shared__ __nv_bfloat16 sbuf[2][3][TILE];
    int m0 = blockIdx.x * 64, n0 = blockIdx.y * 64;
    int b = blockIdx.z >> 3, sk = blockIdx.z & 7;
    int kbeg = sk * KSPLIT;
    int tid = threadIdx.x, warp = tid >> 5, lane = tid & 31;
    int wm = (warp & 1) * 32, wn = (warp >> 1) * 32;

    const __nv_bfloat16* gA1 = g_om + (size_t)b*QP*NP;
    const __nv_bfloat16* gA2 = g_s  + (size_t)b*QP*NP;
    const __nv_bfloat16* gB  = g_tm + (size_t)b*QP*NP;

    int lrow = tid >> 2, lcol = (tid & 3) * 8;

    auto load_stage = [&](int buf, int k0) {
        #pragma unroll
        for (int it = 0; it < 2; it++) {
            int row = lrow + it*32;
            uint32_t d1 = smem_u32(&sbuf[buf][0][row*TPAD + lcol]);
            uint32_t d2 = smem_u32(&sbuf[buf][1][row*TPAD + lcol]);
            uint32_t d3 = smem_u32(&sbuf[buf][2][row*TPAD + lcol]);
            cpasync16(d1, gA1 + (size_t)(m0 + row)*NP + k0 + lcol);
            cpasync16(d2, gA2 + (size_t)(m0 + row)*NP + k0 + lcol);
            cpasync16(d3, gB  + (size_t)(n0 + row)*NP + k0 + lcol);
        }
    };

    float d1[2][4][4], d2[2][4][4];
    #pragma unroll
    for (int mi = 0; mi < 2; mi++)
        #pragma unroll
        for (int nj = 0; nj < 4; nj++)
            #pragma unroll
            for (int e = 0; e < 4; e++) { d1[mi][nj][e] = 0.f; d2[mi][nj][e] = 0.f; }

    int a_r = lane & 15, a_c = ((lane >> 4) & 1) * 8;
    int b_r = (lane & 7) + (((lane & 16) ? 8 : 0)), b_c = ((lane & 8) ? 8 : 0);

    load_stage(0, kbeg);
    cp_commit();

    for (int s = 0; s < NSTAGES; s++) {
        int cur = s & 1;
        if (s + 1 < NSTAGES) {
            load_stage(cur ^ 1, kbeg + (s + 1)*KSTAGE);
            cp_commit();
            cp_wait<1>();
        } else {
            cp_wait<0>();
        }
        __syncthreads();

        const __nv_bfloat16* t1 = sbuf[cur][0];
        const __nv_bfloat16* t2 = sbuf[cur][1];
        const __nv_bfloat16* tB = sbuf[cur][2];
        #pragma unroll
        for (int kk = 0; kk < 2; kk++) {
            uint32_t ao[2][4], as_[2][4], bf[2][4];
            #pragma unroll
            for (int mi = 0; mi < 2; mi++) {
                uint32_t off = (uint32_t)((wm + mi*16 + a_r)*TPAD + kk*16 + a_c)*2;
                ldsm4(ao[mi],  smem_u32(t1) + off);
                ldsm4(as_[mi], smem_u32(t2) + off);
            }
            #pragma unroll
            for (int nb = 0; nb < 2; nb++) {
                uint32_t off = (uint32_t)((wn + nb*16 + b_r)*TPAD + kk*16 + b_c)*2;
                ldsm4(bf[nb], smem_u32(tB) + off);
            }
            #pragma unroll
            for (int mi = 0; mi < 2; mi++)
                #pragma unroll
                for (int nj = 0; nj < 4; nj++) {
                    uint32_t b0 = bf[nj >> 1][(nj & 1)*2], b1 = bf[nj >> 1][(nj & 1)*2 + 1];
                    mma16816(d1[mi][nj], ao[mi],  b0, b1);
                    mma16816(d2[mi][nj], as_[mi], b0, b1);
                }
        }
        __syncthreads();
    }

    float* C1 = g_C1p + (size_t)(sk*BB + b)*NQ*NT;
    float* C2 = g_C2p + (size_t)(sk*BB + b)*NQ*NT;
    int r = lane >> 2, c2 = (lane & 3)*2;
    #pragma unroll
    for (int mi = 0; mi < 2; mi++)
        #pragma unroll
        for (int nj = 0; nj < 4; nj++) {
            int m = m0 + wm + mi*16 + r;
            int n = n0 + wn + nj*8 + c2;
            if (m < NQ) {
                if (n     < NT) { C1[(size_t)m*NT + n]     = d1[mi][nj][0]; C2[(size_t)m*NT + n]     = d2[mi][nj][0]; }
                if (n + 1 < NT) { C1[(size_t)m*NT + n + 1] = d1[mi][nj][1]; C2[(size_t)m*NT + n + 1] = d2[mi][nj][1]; }
            }
            if (m + 8 < NQ) {
                if (n     < NT) { C1[(size_t)(m+8)*NT + n]     = d1[mi][nj][2]; C2[(size_t)(m+8)*NT + n]     = d2[mi][nj][2]; }
                if (n + 1 < NT) { C1[(size_t)(m+8)*NT + n + 1] = d1[mi][nj][3]; C2[(size_t)(m+8)*NT + n + 1] = d2[mi][nj][3]; }
            }
        }
}

// ---------------- K3: final cost --------------------------------------------
__global__ void k_final(const float* __restrict__ pb, const float* __restrict__ tb,
                        float* __restrict__ out) {
    int idx = blockIdx.x * 256 + threadIdx.x;
    if (idx >= BB*NQ*NT) return;
    int t = idx % NT; int r = idx / NT; int q = r % NQ; int b = r / NQ;

    float c1 = 0.f, c2 = 0.f;
    #pragma unroll
    for (int sk = 0; sk < SPLITK; sk++) {
        size_t off = ((size_t)(sk*BB + b)*NQ + q)*NT + t;
        c1 += g_C1p[off]; c2 += g_C2p[off];
    }
    float neg = g_negP[b*NQ + q] + g_negP[BB*NQ + b*NQ + q];
    float ss  = g_sP  [b*NQ + q] + g_sP  [BB*NQ + b*NQ + q];
    float ts  = g_tmsum[b*NT + t];
    float cost_mask = (neg - c1) * (1.0f/(float)NP);
    float cost_dice = 1.f - (2.f*c2 + 1.f) / (ss + ts + 1.f);

    float4 pbox = ((const float4*)pb)[(size_t)b*NQ + q];
    float4 tbox = ((const float4*)tb)[(size_t)b*NT + t];
    float l1 = fabsf(pbox.x - tbox.x) + fabsf(pbox.y - tbox.y)
             + fabsf(pbox.z - tbox.z) + fabsf(pbox.w - tbox.w);

    float ax0 = pbox.x - 0.5f*pbox.z, ay0 = pbox.y - 0.5f*pbox.w;
    float ax1 = pbox.x + 0.5f*pbox.z, ay1 = pbox.y + 0.5f*pbox.w;
    float bx0 = tbox.x - 0.5f*tbox.z, by0 = tbox.y - 0.5f*tbox.w;
    float bx1 = tbox.x + 0.5f*tbox.z, by1 = tbox.y + 0.5f*tbox.w;
    float areaA = (ax1 - ax0)*(ay1 - ay0);
    float areaB = (bx1 - bx0)*(by1 - by0);
    float iw = fmaxf(fminf(ax1, bx1) - fmaxf(ax0, bx0), 0.f);
    float ih = fmaxf(fminf(ay1, by1) - fmaxf(ay0, by0), 0.f);
    float inter = iw * ih;
    float uni = areaA + areaB - inter;
    float iou = inter / uni;
    float ew = fmaxf(fmaxf(ax1, bx1) - fminf(ax0, bx0), 0.f);
    float eh = fmaxf(fmaxf(ay1, by1) - fminf(ay0, by0), 0.f);
    float areaE = ew * eh;
    float giou = iou - (areaE - uni) / areaE;

    out[idx] = 5.f*cost_mask + 5.f*cost_dice + 5.f*l1 - 2.f*giou;
}

// ---------------- launch ------------------------------------------------------
extern "C" void kernel_launch(void* const* d_in, const int* in_sizes, int n_in,
                              void* d_out, int out_size) {
    const float* pred_masks = (const float*)d_in[0];
    const float* tgt_masks  = (const float*)d_in[1];
    const float* pred_boxes = (const float*)d_in[2];
    const float* tgt_boxes  = (const float*)d_in[3];
    const float* pts        = (const float*)d_in[4];
    float* out = (float*)d_out;

    const int smem_pred = 129*IW*2 + 1024*4;   // 66048 + 4096
    cudaFuncSetAttribute(k_sample_pred, cudaFuncAttributeMaxDynamicSharedMemorySize, smem_pred);

    k_sample_tgt <<<dim3(NT, BB), 512>>>(tgt_masks, pts);
    k_sample_pred<<<dim3(NQ, BB, 2), 1024, smem_pred>>>(pred_masks, pts);
    k_gemm<<<dim3(5, 5, BB*SPLITK), 128>>>();
    k_final<<<(BB*NQ*NT + 255)/256, 256>>>(pred_boxes, tgt_boxes, out);
}

// round 4
// speedup vs baseline: 1.6039x; 1.0734x over previous
#include <cuda_runtime.h>
#include <cuda_bf16.h>
#include <cstdint>

#define BB 2
#define NQ 300
#define NT 300
#define QP 320
#define IH 256
#define IW 256
#define HW 65536
#define NP 12544
#define SPLITK 8
#define KSPLIT (NP/SPLITK)      // 1568
#define KSTAGE 32
#define NSTAGES (KSPLIT/KSTAGE) // 49

// ---------------- scratch ----------------
__device__ __nv_bfloat16 g_om[(size_t)BB*QP*NP];   // [b][q][p]
__device__ __nv_bfloat16 g_s [(size_t)BB*QP*NP];
__device__ __nv_bfloat16 g_tm[(size_t)BB*QP*NP];
__device__ float g_negP[2*BB*NQ];                  // per-half partials
__device__ float g_sP  [2*BB*NQ];
__device__ float g_tmsum[BB*NT];
__device__ float g_C1p[(size_t)SPLITK*BB*NQ*NT];
__device__ float g_C2p[(size_t)SPLITK*BB*NQ*NT];

static __device__ __forceinline__ uint32_t smem_u32(const void* p) {
    return (uint32_t)__cvta_generic_to_shared(p);
}
static __device__ __forceinline__ void cpasync16(uint32_t dst, const void* src) {
    asm volatile("cp.async.cg.shared.global [%0], [%1], 16;\n" :: "r"(dst), "l"(src));
}
static __device__ __forceinline__ void cp_commit() { asm volatile("cp.async.commit_group;\n"); }
template<int N> static __device__ __forceinline__ void cp_wait() {
    asm volatile("cp.async.wait_group %0;\n" :: "n"(N));
}

// deterministic warp-tree reduce (fixed shuffle order)
static __device__ __forceinline__ float warp_sum(float v) {
    #pragma unroll
    for (int o = 16; o > 0; o >>= 1) v += __shfl_xor_sync(0xffffffffu, v, o);
    return v;
}

// ---------- K1a: pred sampler, half-mask per CTA (129 rows, 66KB smem) -------
__global__ __launch_bounds__(1024, 2)
void k_sample_pred(const float* __restrict__ pred, const float* __restrict__ pts) {
    extern __shared__ char sraw[];
    __nv_bfloat16* smask = (__nv_bfloat16*)sraw;   // up to 129*256 bf16
    float* rbuf = (float*)(sraw + 129*IW*2);       // 64 floats
    int q = blockIdx.x, b = blockIdx.y, h = blockIdx.z;
    int tid = threadIdx.x, warp = tid >> 5, lane = tid & 31;

    int rows = h ? 128 : 129;                       // guard row only for half 0
    const float* src = pred + ((size_t)(b*NQ + q))*HW + (size_t)h*128*IW;
    const float4* s4 = (const float4*)src;
    int n4 = rows * IW / 4;
    #pragma unroll 4
    for (int i = tid; i < n4; i += 1024) {
        float4 v = s4[i];
        __nv_bfloat162 p0 = __floats2bfloat162_rn(v.x, v.y);
        __nv_bfloat162 p1 = __floats2bfloat162_rn(v.z, v.w);
        uint2 u; u.x = *(uint32_t*)&p0; u.y = *(uint32_t*)&p1;
        ((uint2*)smask)[i] = u;
    }
    __syncthreads();

    const float2* pp = ((const float2*)pts) + (size_t)b*NP;
    size_t obase = ((size_t)(b*QP + q))*NP;
    float accA = 0.f, accB = 0.f;

    for (int p = tid; p < NP; p += 1024) {
        float2 pc = pp[p];
        float y = pc.y * IH - 0.5f;
        float y0f = floorf(y);
        int iy0 = (int)y0f;
        bool own = h ? (iy0 >= 128) : (iy0 < 128);
        if (!own) continue;
        float x = pc.x * IW - 0.5f;
        float x0f = floorf(x);
        float wx = x - x0f, wy = y - y0f;
        int ix0 = (int)x0f;
        float vx0 = (ix0 >= 0) ? 1.f : 0.f;
        float vx1 = (ix0 + 1 <= IW - 1) ? 1.f : 0.f;
        float vy0 = (iy0 >= 0) ? 1.f : 0.f;
        float vy1 = (iy0 + 1 <= IH - 1) ? 1.f : 0.f;
        int xc0 = max(ix0, 0), xc1 = min(ix0 + 1, IW - 1);
        int yl0 = max(iy0, 0) - h*128;
        int yl1 = min(iy0 + 1, IH - 1) - h*128;
        float w00 = (1.f-wy)*(1.f-wx)*vy0*vx0;
        float w01 = (1.f-wy)*wx*vy0*vx1;
        float w10 = wy*(1.f-wx)*vy1*vx0;
        float w11 = wy*wx*vy1*vx1;
        float v = w00*__bfloat162float(smask[yl0*IW + xc0])
                + w01*__bfloat162float(smask[yl0*IW + xc1])
                + w10*__bfloat162float(smask[yl1*IW + xc0])
                + w11*__bfloat162float(smask[yl1*IW + xc1]);
        float e = __expf(-fabsf(v));
        float t = 1.f + e;
        float inv = __fdividef(1.f, t);
        float s = (v >= 0.f) ? inv : e * inv;
        float sp = fmaxf(v, 0.f) + __logf(t);
        accA += sp; accB += s;
        g_om[obase + p] = __float2bfloat16(v);
        g_s [obase + p] = __float2bfloat16(s);
    }

    accA = warp_sum(accA);
    accB = warp_sum(accB);
    if (lane == 0) { rbuf[warp] = accA; rbuf[32 + warp] = accB; }
    __syncthreads();
    if (warp == 0) {
        float a = rbuf[lane];
        float bsum = rbuf[32 + lane];
        a = warp_sum(a);
        bsum = warp_sum(bsum);
        if (lane == 0) {
            g_negP[h*BB*NQ + b*NQ + q] = a;
            g_sP  [h*BB*NQ + b*NQ + q] = bsum;
        }
    }
}

// ---------- K1b: tgt sampler, bit-packed mask (8KB smem), 4 CTAs/SM ----------
__global__ __launch_bounds__(512, 4)
void k_sample_tgt(const float* __restrict__ tgt, const float* __restrict__ pts) {
    __shared__ uint32_t sbits[HW/32];   // 2048 words = 8KB
    __shared__ float rbuf[16];
    int q = blockIdx.x, b = blockIdx.y;
    int tid = threadIdx.x, warp = tid >> 5, lane = tid & 31;

    const float* src = tgt + ((size_t)(b*NT + q))*HW;
    #pragma unroll 4
    for (int w = warp; w < HW/32; w += 16) {
        float v = src[w*32 + lane];
        uint32_t m = __ballot_sync(0xffffffffu, v != 0.0f);
        if (lane == 0) sbits[w] = m;
    }
    __syncthreads();

    const float2* pp = ((const float2*)pts) + (size_t)b*NP;
    size_t obase = ((size_t)(b*QP + q))*NP;
    float acc = 0.f;

    for (int p = tid; p < NP; p += 512) {
        float2 pc = pp[p];
        float x = pc.x * IW - 0.5f, y = pc.y * IH - 0.5f;
        float x0f = floorf(x), y0f = floorf(y);
        float wx = x - x0f, wy = y - y0f;
        int ix0 = (int)x0f, iy0 = (int)y0f;
        float vx0 = (ix0 >= 0) ? 1.f : 0.f;
        float vx1 = (ix0 + 1 <= IW - 1) ? 1.f : 0.f;
        float vy0 = (iy0 >= 0) ? 1.f : 0.f;
        float vy1 = (iy0 + 1 <= IH - 1) ? 1.f : 0.f;
        int xc0 = max(ix0, 0), xc1 = min(ix0 + 1, IW - 1);
        int yc0 = max(iy0, 0), yc1 = min(iy0 + 1, IH - 1);
        int r0 = yc0 * IW, r1 = yc1 * IW;
        float b00 = (float)((sbits[(r0 + xc0) >> 5] >> (xc0 & 31)) & 1u);
        float b01 = (float)((sbits[(r0 + xc1) >> 5] >> (xc1 & 31)) & 1u);
        float b10 = (float)((sbits[(r1 + xc0) >> 5] >> (xc0 & 31)) & 1u);
        float b11 = (float)((sbits[(r1 + xc1) >> 5] >> (xc1 & 31)) & 1u);
        float w00 = (1.f-wy)*(1.f-wx)*vy0*vx0;
        float w01 = (1.f-wy)*wx*vy0*vx1;
        float w10 = wy*(1.f-wx)*vy1*vx0;
        float w11 = wy*wx*vy1*vx1;
        float v = w00*b00 + w01*b01 + w10*b10 + w11*b11;
        acc += v;
        g_tm[obase + p] = __float2bfloat16(v);
    }

    acc = warp_sum(acc);
    if (lane == 0) rbuf[warp] = acc;
    __syncthreads();
    if (warp == 0 && lane < 16) {
        float a = rbuf[lane];
        #pragma unroll
        for (int o = 8; o > 0; o >>= 1) a += __shfl_xor_sync(0xffffu, a, o);
        if (lane == 0) g_tmsum[b*NT + q] = a;
    }
}

// ---------------- K2: dual bf16 GEMM, 3-stage cp.async ring ------------------
__device__ __forceinline__ void ldsm4(uint32_t* r, uint32_t addr) {
    asm volatile("ldmatrix.sync.aligned.m8n8.x4.shared.b16 {%0,%1,%2,%3}, [%4];"
        : "=r"(r[0]), "=r"(r[1]), "=r"(r[2]), "=r"(r[3]) : "r"(addr));
}
__device__ __forceinline__ void mma16816(float* d, const uint32_t* a, uint32_t b0, uint32_t b1) {
    asm volatile("mma.sync.aligned.m16n8k16.row.col.f32.bf16.bf16.f32 "
        "{%0,%1,%2,%3}, {%4,%5,%6,%7}, {%8,%9}, {%0,%1,%2,%3};"
        : "+f"(d[0]), "+f"(d[1]), "+f"(d[2]), "+f"(d[3])
        : "r"(a[0]), "r"(a[1]), "r"(a[2]), "r"(a[3]), "r"(b0), "r"(b1));
}

#define TPAD 40
#define TILE (64*TPAD)

__global__ __launch_bounds__(128) void k_gemm() {
    __shared__ __nv_bfloat16 sbuf[3][3][TILE];   // [stage][om,s,tm]
    int m0 = blockIdx.x * 64, n0 = blockIdx.y * 64;
    int b = blockIdx.z >> 3, sk = blockIdx.z & 7;
    int kbeg = sk * KSPLIT;
    int tid = threadIdx.x, warp = tid >> 5, lane = tid & 31;
    int wm = (warp & 1) * 32, wn = (warp >> 1) * 32;

    const __nv_bfloat16* gA1 = g_om + (size_t)b*QP*NP;
    const __nv_bfloat16* gA2 = g_s  + (size_t)b*QP*NP;
    const __nv_bfloat16* gB  = g_tm + (size_t)b*QP*NP;

    int lrow = tid >> 2, lcol = (tid & 3) * 8;

    auto load_stage = [&](int buf, int k0) {
        #pragma unroll
        for (int it = 0; it < 2; it++) {
            int row = lrow + it*32;
            uint32_t d1 = smem_u32(&sbuf[buf][0][row*TPAD + lcol]);
            uint32_t d2 = smem_u32(&sbuf[buf][1][row*TPAD + lcol]);
            uint32_t d3 = smem_u32(&sbuf[buf][2][row*TPAD + lcol]);
            cpasync16(d1, gA1 + (size_t)(m0 + row)*NP + k0 + lcol);
            cpasync16(d2, gA2 + (size_t)(m0 + row)*NP + k0 + lcol);
            cpasync16(d3, gB  + (size_t)(n0 + row)*NP + k0 + lcol);
        }
    };

    float d1[2][4][4], d2[2][4][4];
    #pragma unroll
    for (int mi = 0; mi < 2; mi++)
        #pragma unroll
        for (int nj = 0; nj < 4; nj++)
            #pragma unroll
            for (int e = 0; e < 4; e++) { d1[mi][nj][e] = 0.f; d2[mi][nj][e] = 0.f; }

    int a_r = lane & 15, a_c = ((lane >> 4) & 1) * 8;
    int b_r = (lane & 7) + (((lane & 16) ? 8 : 0)), b_c = ((lane & 8) ? 8 : 0);

    load_stage(0, kbeg);            cp_commit();
    load_stage(1, kbeg + KSTAGE);   cp_commit();

    for (int s = 0; s < NSTAGES; s++) {
        if (s + 1 < NSTAGES) cp_wait<1>(); else cp_wait<0>();
        __syncthreads();
        if (s + 2 < NSTAGES) {
            load_stage((s + 2) % 3, kbeg + (s + 2)*KSTAGE);
            cp_commit();
        }

        int cur = s % 3;
        const __nv_bfloat16* t1 = sbuf[cur][0];
        const __nv_bfloat16* t2 = sbuf[cur][1];
        const __nv_bfloat16* tB = sbuf[cur][2];
        #pragma unroll
        for (int kk = 0; kk < 2; kk++) {
            uint32_t ao[2][4], as_[2][4], bf[2][4];
            #pragma unroll
            for (int mi = 0; mi < 2; mi++) {
                uint32_t off = (uint32_t)((wm + mi*16 + a_r)*TPAD + kk*16 + a_c)*2;
                ldsm4(ao[mi],  smem_u32(t1) + off);
                ldsm4(as_[mi], smem_u32(t2) + off);
            }
            #pragma unroll
            for (int nb = 0; nb < 2; nb++) {
                uint32_t off = (uint32_t)((wn + nb*16 + b_r)*TPAD + kk*16 + b_c)*2;
                ldsm4(bf[nb], smem_u32(tB) + off);
            }
            #pragma unroll
            for (int mi = 0; mi < 2; mi++)
                #pragma unroll
                for (int nj = 0; nj < 4; nj++) {
                    uint32_t b0 = bf[nj >> 1][(nj & 1)*2], b1 = bf[nj >> 1][(nj & 1)*2 + 1];
                    mma16816(d1[mi][nj], ao[mi],  b0, b1);
                    mma16816(d2[mi][nj], as_[mi], b0, b1);
                }
        }
    }

    float* C1 = g_C1p + (size_t)(sk*BB + b)*NQ*NT;
    float* C2 = g_C2p + (size_t)(sk*BB + b)*NQ*NT;
    int r = lane >> 2, c2 = (lane & 3)*2;
    #pragma unroll
    for (int mi = 0; mi < 2; mi++)
        #pragma unroll
        for (int nj = 0; nj < 4; nj++) {
            int m = m0 + wm + mi*16 + r;
            int n = n0 + wn + nj*8 + c2;
            if (m < NQ) {
                if (n     < NT) { C1[(size_t)m*NT + n]     = d1[mi][nj][0]; C2[(size_t)m*NT + n]     = d2[mi][nj][0]; }
                if (n + 1 < NT) { C1[(size_t)m*NT + n + 1] = d1[mi][nj][1]; C2[(size_t)m*NT + n + 1] = d2[mi][nj][1]; }
            }
            if (m + 8 < NQ) {
                if (n     < NT) { C1[(size_t)(m+8)*NT + n]     = d1[mi][nj][2]; C2[(size_t)(m+8)*NT + n]     = d2[mi][nj][2]; }
                if (n + 1 < NT) { C1[(size_t)(m+8)*NT + n + 1] = d1[mi][nj][3]; C2[(size_t)(m+8)*NT + n + 1] = d2[mi][nj][3]; }
            }
        }
}

// ---------------- K3: final cost --------------------------------------------
__global__ void k_final(const float* __restrict__ pb, const float* __restrict__ tb,
                        float* __restrict__ out) {
    int idx = blockIdx.x * 256 + threadIdx.x;
    if (idx >= BB*NQ*NT) return;
    int t = idx % NT; int r = idx / NT; int q = r % NQ; int b = r / NQ;

    float c1 = 0.f, c2 = 0.f;
    #pragma unroll
    for (int sk = 0; sk < SPLITK; sk++) {
        size_t off = ((size_t)(sk*BB + b)*NQ + q)*NT + t;
        c1 += g_C1p[off]; c2 += g_C2p[off];
    }
    float neg = g_negP[b*NQ + q] + g_negP[BB*NQ + b*NQ + q];
    float ss  = g_sP  [b*NQ + q] + g_sP  [BB*NQ + b*NQ + q];
    float ts  = g_tmsum[b*NT + t];
    float cost_mask = (neg - c1) * (1.0f/(float)NP);
    float cost_dice = 1.f - (2.f*c2 + 1.f) / (ss + ts + 1.f);

    float4 pbox = ((const float4*)pb)[(size_t)b*NQ + q];
    float4 tbox = ((const float4*)tb)[(size_t)b*NT + t];
    float l1 = fabsf(pbox.x - tbox.x) + fabsf(pbox.y - tbox.y)
             + fabsf(pbox.z - tbox.z) + fabsf(pbox.w - tbox.w);

    float ax0 = pbox.x - 0.5f*pbox.z, ay0 = pbox.y - 0.5f*pbox.w;
    float ax1 = pbox.x + 0.5f*pbox.z, ay1 = pbox.y + 0.5f*pbox.w;
    float bx0 = tbox.x - 0.5f*tbox.z, by0 = tbox.y - 0.5f*tbox.w;
    float bx1 = tbox.x + 0.5f*tbox.z, by1 = tbox.y + 0.5f*tbox.w;
    float areaA = (ax1 - ax0)*(ay1 - ay0);
    float areaB = (bx1 - bx0)*(by1 - by0);
    float iw = fmaxf(fminf(ax1, bx1) - fmaxf(ax0, bx0), 0.f);
    float ih = fmaxf(fminf(ay1, by1) - fmaxf(ay0, by0), 0.f);
    float inter = iw * ih;
    float uni = areaA + areaB - inter;
    float iou = inter / uni;
    float ew = fmaxf(fmaxf(ax1, bx1) - fminf(ax0, bx0), 0.f);
    float eh = fmaxf(fmaxf(ay1, by1) - fminf(ay0, by0), 0.f);
    float areaE = ew * eh;
    float giou = iou - (areaE - uni) / areaE;

    out[idx] = 5.f*cost_mask + 5.f*cost_dice + 5.f*l1 - 2.f*giou;
}

// ---------------- launch ------------------------------------------------------
extern "C" void kernel_launch(void* const* d_in, const int* in_sizes, int n_in,
                              void* d_out, int out_size) {
    const float* pred_masks = (const float*)d_in[0];
    const float* tgt_masks  = (const float*)d_in[1];
    const float* pred_boxes = (const float*)d_in[2];
    const float* tgt_boxes  = (const float*)d_in[3];
    const float* pts        = (const float*)d_in[4];
    float* out = (float*)d_out;

    // one-time host resources (created on the first, non-captured, correctness
    // call; only reused thereafter — identical work every call)
    static cudaStream_t side = []() {
        cudaStream_t s; cudaStreamCreateWithFlags(&s, cudaStreamNonBlocking); return s;
    }();
    static cudaEvent_t evFork = []() {
        cudaEvent_t e; cudaEventCreateWithFlags(&e, cudaEventDisableTiming); return e;
    }();
    static cudaEvent_t evJoin = []() {
        cudaEvent_t e; cudaEventCreateWithFlags(&e, cudaEventDisableTiming); return e;
    }();
    static bool attr_done = []() {
        cudaFuncSetAttribute(k_sample_pred, cudaFuncAttributeMaxDynamicSharedMemorySize,
                             129*IW*2 + 64*4);
        return true;
    }();
    (void)attr_done;

    const int smem_pred = 129*IW*2 + 64*4;

    // fork: tgt sampler on side stream, pred sampler on main stream
    cudaEventRecord(evFork, 0);
    cudaStreamWaitEvent(side, evFork, 0);
    k_sample_tgt <<<dim3(NT, BB), 512, 0, side>>>(tgt_masks, pts);
    k_sample_pred<<<dim3(NQ, BB, 2), 1024, smem_pred>>>(pred_masks, pts);
    cudaEventRecord(evJoin, side);
    cudaStreamWaitEvent(0, evJoin, 0);

    k_gemm<<<dim3(5, 5, BB*SPLITK), 128>>>();
    k_final<<<(BB*NQ*NT + 255)/256, 256>>>(pred_boxes, tgt_boxes, out);
}